// round 3
// baseline (speedup 1.0000x reference)
#include <cuda_runtime.h>
#include <cuda_bf16.h>

// ---------------------------------------------------------------------------
// Swin shifted-window attention, fp32 baseline. (R2 resubmit: R1/R2 benches
// were broker/container acquisition failures — kernel never executed.)
// Stage 1: roll(-3,-3) fused QKV GEMM -> windowed Q/K/V scratch
// Stage 2: per-(window,head) attention (bias + shift masks + softmax) -> token layout
// Stage 3: output projection GEMM + bias, roll(+3,+3) fused into store
// ---------------------------------------------------------------------------

#define B_     16
#define HW     56
#define EMB    384
#define HEADS  12
#define HD     32
#define WS     7
#define NTOK   49          // tokens per window
#define NWIN   64          // windows per image (8x8)
#define TOKENS (B_*HW*HW)  // 50176

#define BM 128
#define BN 128
#define BK 16
#define TM 8
#define TN 8

// Scratch (device globals; no allocation allowed)
__device__ float g_q[B_*NWIN*HEADS*NTOK*HD];
__device__ float g_k[B_*NWIN*HEADS*NTOK*HD];
__device__ float g_v[B_*NWIN*HEADS*NTOK*HD];
__device__ float g_ao[TOKENS*EMB];

// ---------------------------------------------------------------------------
// Stage 1: QKV GEMM. A = rolled x (50176 x 384), B = w_qkv (1152 x 384),
// C[i][j] = sum_k A[i][k]*B[j][k]. Scatter into windowed q/k/v layout.
// ---------------------------------------------------------------------------
__global__ __launch_bounds__(256) void qkv_gemm(const float* __restrict__ x,
                                                const float* __restrict__ wqkv) {
    __shared__ float As[BK][BM];
    __shared__ float Bs[BK][BN];
    const int tid  = threadIdx.x;
    const int row0 = blockIdx.y * BM;
    const int col0 = blockIdx.x * BN;
    const int tr   = (tid >> 4) * TM;
    const int tc   = (tid & 15) * TN;

    float acc[TM][TN];
#pragma unroll
    for (int i = 0; i < TM; i++)
#pragma unroll
        for (int j = 0; j < TN; j++) acc[i][j] = 0.f;

    // each thread loads 2 float4 from A and 2 from B per k-step
    const int lr0 = tid >> 2;       // 0..63
    const int c4  = tid & 3;        // which float4 of 16-col slab
    const float* arow[2];
    const float* brow[2];
#pragma unroll
    for (int l = 0; l < 2; l++) {
        int r = lr0 + l * 64;
        int m = row0 + r;
        int b = m / 3136, rem = m % 3136, h = rem / HW, w = rem % HW;
        int hs = (h + 3) % HW, ws = (w + 3) % HW;   // roll(-3,-3)
        arow[l] = x + ((b * HW + hs) * HW + ws) * EMB;
        brow[l] = wqkv + (col0 + r) * EMB;
    }

    for (int k0 = 0; k0 < EMB; k0 += BK) {
#pragma unroll
        for (int l = 0; l < 2; l++) {
            int r = lr0 + l * 64;
            float4 a = *(const float4*)(arow[l] + k0 + c4 * 4);
            As[c4*4+0][r] = a.x; As[c4*4+1][r] = a.y;
            As[c4*4+2][r] = a.z; As[c4*4+3][r] = a.w;
            float4 bv = *(const float4*)(brow[l] + k0 + c4 * 4);
            Bs[c4*4+0][r] = bv.x; Bs[c4*4+1][r] = bv.y;
            Bs[c4*4+2][r] = bv.z; Bs[c4*4+3][r] = bv.w;
        }
        __syncthreads();
#pragma unroll
        for (int kk = 0; kk < BK; kk++) {
            float af[TM], bf[TN];
            *(float4*)&af[0] = *(float4*)&As[kk][tr];
            *(float4*)&af[4] = *(float4*)&As[kk][tr + 4];
            *(float4*)&bf[0] = *(float4*)&Bs[kk][tc];
            *(float4*)&bf[4] = *(float4*)&Bs[kk][tc + 4];
#pragma unroll
            for (int i = 0; i < TM; i++)
#pragma unroll
                for (int j = 0; j < TN; j++) acc[i][j] = fmaf(af[i], bf[j], acc[i][j]);
        }
        __syncthreads();
    }

    // scatter epilogue: windowed layout idx = (b*64+win)*18816 + head*1568 + n*32 + d
    const int sel = col0 / EMB;                   // whole 128-wide tile is one of q/k/v
    float* dst = (sel == 0) ? g_q : (sel == 1) ? g_k : g_v;
#pragma unroll
    for (int i = 0; i < TM; i++) {
        int m = row0 + tr + i;
        int b = m / 3136, rem = m % 3136, h = rem / HW, w = rem % HW;
        int win = (h / WS) * 8 + (w / WS);
        int n   = (h % WS) * WS + (w % WS);
        int rowoff = (b * NWIN + win) * (HEADS * NTOK * HD) + n * HD;
#pragma unroll
        for (int j = 0; j < TN; j++) {
            int col  = col0 + tc + j - sel * EMB;
            int head = col >> 5, d = col & 31;
            dst[rowoff + head * (NTOK * HD) + d] = acc[i][j];
        }
    }
}

// ---------------------------------------------------------------------------
// Stage 2: attention. One block per (b, win, head). 256 threads.
// ---------------------------------------------------------------------------
__global__ __launch_bounds__(256) void attn_kernel(const float* __restrict__ pe_g) {
    __shared__ float q[NTOK * HD];
    __shared__ float k[NTOK * HD];
    __shared__ float v[NTOK * HD];
    __shared__ float sc[NTOK][NTOK + 1];
    __shared__ float pe[169];

    const int blk = blockIdx.x;      // (b*64+win)*12 + head
    const int tid = threadIdx.x;
    const float* qp = g_q + blk * (NTOK * HD);
    const float* kp = g_k + blk * (NTOK * HD);
    const float* vp = g_v + blk * (NTOK * HD);

    for (int i4 = tid; i4 < NTOK * HD / 4; i4 += 256) {
        ((float4*)q)[i4] = ((const float4*)qp)[i4];
        ((float4*)k)[i4] = ((const float4*)kp)[i4];
        ((float4*)v)[i4] = ((const float4*)vp)[i4];
    }
    if (tid < 169) pe[tid] = pe_g[tid];
    __syncthreads();

    const int head = blk % HEADS;
    const int bwin = blk / HEADS;
    const int win  = bwin & 63;
    const int b    = bwin >> 6;
    const bool mUL = (win >= 56);          // last window row
    const bool mLR = ((win & 7) == 7);     // last window col
    const float scale = 0.17677669529663687f;  // 1/sqrt(32)

    // scores + bias + masks
    for (int idx = tid; idx < NTOK * NTOK; idx += 256) {
        int i = idx / NTOK, j = idx - i * NTOK;
        const float* qi = q + i * HD;
        const float* kj = k + j * HD;
        float s = 0.f;
#pragma unroll
        for (int d = 0; d < HD; d++) s = fmaf(qi[d], kj[d], s);
        int xi = i / WS, yi = i - xi * WS;
        int xj = j / WS, yj = j - xj * WS;
        s = s * scale + pe[(xj - xi + 6) * 13 + (yj - yi + 6)];
        bool dead = (mUL && ((i >= 28) != (j >= 28))) ||
                    (mLR && ((yi >= 4) != (yj >= 4)));
        sc[i][j] = dead ? -1e30f : s;
    }
    __syncthreads();

    // softmax: one row per warp, round-robin
    const int warp = tid >> 5, lane = tid & 31;
    for (int i = warp; i < NTOK; i += 8) {
        float mx = -1e30f;
        for (int j = lane; j < NTOK; j += 32) mx = fmaxf(mx, sc[i][j]);
#pragma unroll
        for (int o = 16; o; o >>= 1) mx = fmaxf(mx, __shfl_xor_sync(0xffffffffu, mx, o));
        float sum = 0.f;
        for (int j = lane; j < NTOK; j += 32) {
            float e = __expf(sc[i][j] - mx);
            sc[i][j] = e;
            sum += e;
        }
#pragma unroll
        for (int o = 16; o; o >>= 1) sum += __shfl_xor_sync(0xffffffffu, sum, o);
        float inv = 1.0f / sum;
        for (int j = lane; j < NTOK; j += 32) sc[i][j] *= inv;
    }
    __syncthreads();

    // out = attn @ V, write to token layout (rolled coordinate space)
    const int h0 = (win >> 3) * WS, w0 = (win & 7) * WS;
    for (int idx = tid; idx < NTOK * HD; idx += 256) {
        int i = idx >> 5, d = idx & 31;
        float o = 0.f;
#pragma unroll
        for (int j = 0; j < NTOK; j++) o = fmaf(sc[i][j], v[j * HD + d], o);
        int h = h0 + i / WS, w = w0 + i % WS;
        g_ao[((b * HW + h) * HW + w) * EMB + head * HD + d] = o;
    }
}

// ---------------------------------------------------------------------------
// Stage 3: projection GEMM. A = g_ao (50176 x 384), B = w_out (384 x 384),
// out[(h+3)%56][(w+3)%56][j] = C[i][j] + b_out[j]   (roll +3,+3)
// ---------------------------------------------------------------------------
__global__ __launch_bounds__(256) void proj_gemm(const float* __restrict__ wout,
                                                 const float* __restrict__ bout,
                                                 float* __restrict__ out) {
    __shared__ float As[BK][BM];
    __shared__ float Bs[BK][BN];
    const int tid  = threadIdx.x;
    const int row0 = blockIdx.y * BM;
    const int col0 = blockIdx.x * BN;
    const int tr   = (tid >> 4) * TM;
    const int tc   = (tid & 15) * TN;

    float acc[TM][TN];
#pragma unroll
    for (int i = 0; i < TM; i++)
#pragma unroll
        for (int j = 0; j < TN; j++) acc[i][j] = 0.f;

    const int lr0 = tid >> 2;
    const int c4  = tid & 3;
    const float* arow[2];
    const float* brow[2];
#pragma unroll
    for (int l = 0; l < 2; l++) {
        int r = lr0 + l * 64;
        arow[l] = g_ao + (row0 + r) * EMB;
        brow[l] = wout + (col0 + r) * EMB;
    }

    for (int k0 = 0; k0 < EMB; k0 += BK) {
#pragma unroll
        for (int l = 0; l < 2; l++) {
            int r = lr0 + l * 64;
            float4 a = *(const float4*)(arow[l] + k0 + c4 * 4);
            As[c4*4+0][r] = a.x; As[c4*4+1][r] = a.y;
            As[c4*4+2][r] = a.z; As[c4*4+3][r] = a.w;
            float4 bv = *(const float4*)(brow[l] + k0 + c4 * 4);
            Bs[c4*4+0][r] = bv.x; Bs[c4*4+1][r] = bv.y;
            Bs[c4*4+2][r] = bv.z; Bs[c4*4+3][r] = bv.w;
        }
        __syncthreads();
#pragma unroll
        for (int kk = 0; kk < BK; kk++) {
            float af[TM], bf[TN];
            *(float4*)&af[0] = *(float4*)&As[kk][tr];
            *(float4*)&af[4] = *(float4*)&As[kk][tr + 4];
            *(float4*)&bf[0] = *(float4*)&Bs[kk][tc];
            *(float4*)&bf[4] = *(float4*)&Bs[kk][tc + 4];
#pragma unroll
            for (int i = 0; i < TM; i++)
#pragma unroll
                for (int j = 0; j < TN; j++) acc[i][j] = fmaf(af[i], bf[j], acc[i][j]);
        }
        __syncthreads();
    }

#pragma unroll
    for (int i = 0; i < TM; i++) {
        int m = row0 + tr + i;
        int b = m / 3136, rem = m % 3136, h = rem / HW, w = rem % HW;
        int ho = (h + 3) % HW, wo = (w + 3) % HW;   // roll(+3,+3)
        float* orow = out + ((b * HW + ho) * HW + wo) * EMB + col0 + tc;
#pragma unroll
        for (int j = 0; j < TN; j++) {
            orow[j] = acc[i][j] + bout[col0 + tc + j];
        }
    }
}

// ---------------------------------------------------------------------------
extern "C" void kernel_launch(void* const* d_in, const int* in_sizes, int n_in,
                              void* d_out, int out_size) {
    const float* x       = (const float*)d_in[0];
    const float* w_qkv   = (const float*)d_in[1];
    const float* pos_emb = (const float*)d_in[2];
    const float* w_out   = (const float*)d_in[3];
    const float* b_out   = (const float*)d_in[4];
    float* out = (float*)d_out;

    dim3 g1(1152 / BN, TOKENS / BM);          // 9 x 392
    qkv_gemm<<<g1, 256>>>(x, w_qkv);

    attn_kernel<<<B_ * NWIN * HEADS, 256>>>(pos_emb);

    dim3 g3(EMB / BN, TOKENS / BM);           // 3 x 392
    proj_gemm<<<g3, 256>>>(w_out, b_out, out);
}

// round 9
// speedup vs baseline: 1.0463x; 1.0463x over previous
#include <cuda_runtime.h>
#include <cuda_bf16.h>

// ---------------------------------------------------------------------------
// Swin shifted-window attention. R8: back to guard-proven pure-FFMA paradigm
// (every tensor-core variant, asm or wmma, got a local-memory frame from ptxas
// and tripped the allocation guard). GEMMs re-tiled for higher flop/smem-byte:
// 128-thread blocks, 8x16 register tile (2.67 flop/B vs R2's 2.0).
// ---------------------------------------------------------------------------

#define B_     16
#define HW     56
#define EMB    384
#define HEADS  12
#define HD     32
#define WS     7
#define NTOK   49          // tokens per window
#define NWIN   64          // windows per image (8x8)
#define TOKENS (B_*HW*HW)  // 50176

#define BM 128
#define BN 128
#define BK 16
#define TM 8               // rows per thread
#define TN 16              // cols per thread
#define NTHR 128           // (BM/TM)*(BN/TN) = 16*8

// Scratch (device globals; guard-sanctioned)
__device__ float g_q[B_*NWIN*HEADS*NTOK*HD];
__device__ float g_k[B_*NWIN*HEADS*NTOK*HD];
__device__ float g_v[B_*NWIN*HEADS*NTOK*HD];
__device__ float g_ao[TOKENS*EMB];

// ---------------------------------------------------------------------------
// Stage 1: QKV GEMM. A = rolled x (50176 x 384), B = w_qkv (1152 x 384),
// C[i][j] = sum_k A[i][k]*B[j][k]. Scatter into windowed q/k/v layout.
// ---------------------------------------------------------------------------
__global__ __launch_bounds__(NTHR) void qkv_gemm(const float* __restrict__ x,
                                                 const float* __restrict__ wqkv) {
    __shared__ float As[BK][BM];
    __shared__ float Bs[BK][BN];
    const int tid  = threadIdx.x;
    const int row0 = blockIdx.y * BM;
    const int col0 = blockIdx.x * BN;
    const int tr   = (tid & 15) * TM;     // 16 M-groups
    const int tc   = (tid >> 4) * TN;     // 8 N-groups

    float acc[TM][TN];
#pragma unroll
    for (int i = 0; i < TM; i++)
#pragma unroll
        for (int j = 0; j < TN; j++) acc[i][j] = 0.f;

    // staging: 4 float4 from A and 4 from B per slab per thread
    const int lr0 = tid >> 2;       // 0..31
    const int c4  = tid & 3;        // which float4 of the 16-col slab
    const float* arow[4];
    const float* brow[4];
#pragma unroll
    for (int l = 0; l < 4; l++) {
        int r = lr0 + l * 32;
        int m = row0 + r;
        int b = m / 3136, rem = m % 3136, h = rem / HW, w = rem % HW;
        int hs = (h + 3) % HW, ws = (w + 3) % HW;   // roll(-3,-3)
        arow[l] = x + ((b * HW + hs) * HW + ws) * EMB;
        brow[l] = wqkv + (col0 + r) * EMB;
    }

    for (int k0 = 0; k0 < EMB; k0 += BK) {
        __syncthreads();
#pragma unroll
        for (int l = 0; l < 4; l++) {
            int r = lr0 + l * 32;
            float4 a = *(const float4*)(arow[l] + k0 + c4 * 4);
            As[c4*4+0][r] = a.x; As[c4*4+1][r] = a.y;
            As[c4*4+2][r] = a.z; As[c4*4+3][r] = a.w;
            float4 bv = *(const float4*)(brow[l] + k0 + c4 * 4);
            Bs[c4*4+0][r] = bv.x; Bs[c4*4+1][r] = bv.y;
            Bs[c4*4+2][r] = bv.z; Bs[c4*4+3][r] = bv.w;
        }
        __syncthreads();
#pragma unroll
        for (int kk = 0; kk < BK; kk++) {
            float af[TM], bf[TN];
            *(float4*)&af[0]  = *(float4*)&As[kk][tr];
            *(float4*)&af[4]  = *(float4*)&As[kk][tr + 4];
            *(float4*)&bf[0]  = *(float4*)&Bs[kk][tc];
            *(float4*)&bf[4]  = *(float4*)&Bs[kk][tc + 4];
            *(float4*)&bf[8]  = *(float4*)&Bs[kk][tc + 8];
            *(float4*)&bf[12] = *(float4*)&Bs[kk][tc + 12];
#pragma unroll
            for (int i = 0; i < TM; i++)
#pragma unroll
                for (int j = 0; j < TN; j++) acc[i][j] = fmaf(af[i], bf[j], acc[i][j]);
        }
    }

    // scatter epilogue: windowed layout idx = (b*64+win)*18816 + head*1568 + n*32 + d
    const int sel = col0 / EMB;                   // whole 128-wide tile is one of q/k/v
    float* dst = (sel == 0) ? g_q : (sel == 1) ? g_k : g_v;
    const int local = col0 + tc - sel * EMB;      // 16-aligned, within one head block
    const int head  = local >> 5;
    const int d0    = local & 31;                 // 0 or 16
#pragma unroll
    for (int i = 0; i < TM; i++) {
        int m = row0 + tr + i;
        int b = m / 3136, rem = m % 3136, h = rem / HW, w = rem % HW;
        int win = (h / WS) * 8 + (w / WS);
        int n   = (h % WS) * WS + (w % WS);
        float* drow = dst + (b * NWIN + win) * (HEADS * NTOK * HD)
                          + head * (NTOK * HD) + n * HD + d0;
#pragma unroll
        for (int j = 0; j < TN; j += 4) {
            *(float4*)&drow[j] = make_float4(acc[i][j], acc[i][j+1], acc[i][j+2], acc[i][j+3]);
        }
    }
}

// ---------------------------------------------------------------------------
// Stage 2: attention. One block per (b, win, head). 256 threads.
// (byte-identical to the R2 version that passed)
// ---------------------------------------------------------------------------
__global__ __launch_bounds__(256) void attn_kernel(const float* __restrict__ pe_g) {
    __shared__ float q[NTOK * HD];
    __shared__ float k[NTOK * HD];
    __shared__ float v[NTOK * HD];
    __shared__ float sc[NTOK][NTOK + 1];
    __shared__ float pe[169];

    const int blk = blockIdx.x;      // (b*64+win)*12 + head
    const int tid = threadIdx.x;
    const float* qp = g_q + blk * (NTOK * HD);
    const float* kp = g_k + blk * (NTOK * HD);
    const float* vp = g_v + blk * (NTOK * HD);

    for (int i4 = tid; i4 < NTOK * HD / 4; i4 += 256) {
        ((float4*)q)[i4] = ((const float4*)qp)[i4];
        ((float4*)k)[i4] = ((const float4*)kp)[i4];
        ((float4*)v)[i4] = ((const float4*)vp)[i4];
    }
    if (tid < 169) pe[tid] = pe_g[tid];
    __syncthreads();

    const int head = blk % HEADS;
    const int bwin = blk / HEADS;
    const int win  = bwin & 63;
    const int b    = bwin >> 6;
    const bool mUL = (win >= 56);          // last window row
    const bool mLR = ((win & 7) == 7);     // last window col
    const float scale = 0.17677669529663687f;  // 1/sqrt(32)

    for (int idx = tid; idx < NTOK * NTOK; idx += 256) {
        int i = idx / NTOK, j = idx - i * NTOK;
        const float* qi = q + i * HD;
        const float* kj = k + j * HD;
        float s = 0.f;
#pragma unroll
        for (int d = 0; d < HD; d++) s = fmaf(qi[d], kj[d], s);
        int xi = i / WS, yi = i - xi * WS;
        int xj = j / WS, yj = j - xj * WS;
        s = s * scale + pe[(xj - xi + 6) * 13 + (yj - yi + 6)];
        bool dead = (mUL && ((i >= 28) != (j >= 28))) ||
                    (mLR && ((yi >= 4) != (yj >= 4)));
        sc[i][j] = dead ? -1e30f : s;
    }
    __syncthreads();

    const int warp = tid >> 5, lane = tid & 31;
    for (int i = warp; i < NTOK; i += 8) {
        float mx = -1e30f;
        for (int j = lane; j < NTOK; j += 32) mx = fmaxf(mx, sc[i][j]);
#pragma unroll
        for (int o = 16; o; o >>= 1) mx = fmaxf(mx, __shfl_xor_sync(0xffffffffu, mx, o));
        float sum = 0.f;
        for (int j = lane; j < NTOK; j += 32) {
            float e = __expf(sc[i][j] - mx);
            sc[i][j] = e;
            sum += e;
        }
#pragma unroll
        for (int o = 16; o; o >>= 1) sum += __shfl_xor_sync(0xffffffffu, sum, o);
        float inv = 1.0f / sum;
        for (int j = lane; j < NTOK; j += 32) sc[i][j] *= inv;
    }
    __syncthreads();

    const int h0 = (win >> 3) * WS, w0 = (win & 7) * WS;
    for (int idx = tid; idx < NTOK * HD; idx += 256) {
        int i = idx >> 5, d = idx & 31;
        float o = 0.f;
#pragma unroll
        for (int j = 0; j < NTOK; j++) o = fmaf(sc[i][j], v[j * HD + d], o);
        int h = h0 + i / WS, w = w0 + i % WS;
        g_ao[((b * HW + h) * HW + w) * EMB + head * HD + d] = o;
    }
}

// ---------------------------------------------------------------------------
// Stage 3: projection GEMM. A = g_ao (50176 x 384), B = w_out (384 x 384),
// out[(h+3)%56][(w+3)%56][:] = C[i][:] + b_out   (roll +3,+3)
// ---------------------------------------------------------------------------
__global__ __launch_bounds__(NTHR) void proj_gemm(const float* __restrict__ wout,
                                                  const float* __restrict__ bout,
                                                  float* __restrict__ out) {
    __shared__ float As[BK][BM];
    __shared__ float Bs[BK][BN];
    const int tid  = threadIdx.x;
    const int row0 = blockIdx.y * BM;
    const int col0 = blockIdx.x * BN;
    const int tr   = (tid & 15) * TM;
    const int tc   = (tid >> 4) * TN;

    float acc[TM][TN];
#pragma unroll
    for (int i = 0; i < TM; i++)
#pragma unroll
        for (int j = 0; j < TN; j++) acc[i][j] = 0.f;

    const int lr0 = tid >> 2;
    const int c4  = tid & 3;
    const float* arow[4];
    const float* brow[4];
#pragma unroll
    for (int l = 0; l < 4; l++) {
        int r = lr0 + l * 32;
        arow[l] = g_ao + (row0 + r) * EMB;
        brow[l] = wout + (col0 + r) * EMB;
    }

    for (int k0 = 0; k0 < EMB; k0 += BK) {
        __syncthreads();
#pragma unroll
        for (int l = 0; l < 4; l++) {
            int r = lr0 + l * 32;
            float4 a = *(const float4*)(arow[l] + k0 + c4 * 4);
            As[c4*4+0][r] = a.x; As[c4*4+1][r] = a.y;
            As[c4*4+2][r] = a.z; As[c4*4+3][r] = a.w;
            float4 bv = *(const float4*)(brow[l] + k0 + c4 * 4);
            Bs[c4*4+0][r] = bv.x; Bs[c4*4+1][r] = bv.y;
            Bs[c4*4+2][r] = bv.z; Bs[c4*4+3][r] = bv.w;
        }
        __syncthreads();
#pragma unroll
        for (int kk = 0; kk < BK; kk++) {
            float af[TM], bf[TN];
            *(float4*)&af[0]  = *(float4*)&As[kk][tr];
            *(float4*)&af[4]  = *(float4*)&As[kk][tr + 4];
            *(float4*)&bf[0]  = *(float4*)&Bs[kk][tc];
            *(float4*)&bf[4]  = *(float4*)&Bs[kk][tc + 4];
            *(float4*)&bf[8]  = *(float4*)&Bs[kk][tc + 8];
            *(float4*)&bf[12] = *(float4*)&Bs[kk][tc + 12];
#pragma unroll
            for (int i = 0; i < TM; i++)
#pragma unroll
                for (int j = 0; j < TN; j++) acc[i][j] = fmaf(af[i], bf[j], acc[i][j]);
        }
    }

#pragma unroll
    for (int i = 0; i < TM; i++) {
        int m = row0 + tr + i;
        int b = m / 3136, rem = m % 3136, h = rem / HW, w = rem % HW;
        int ho = (h + 3) % HW, wo = (w + 3) % HW;   // roll(+3,+3)
        float* orow = out + ((b * HW + ho) * HW + wo) * EMB + col0 + tc;
#pragma unroll
        for (int j = 0; j < TN; j += 4) {
            float4 bb = *(const float4*)&bout[col0 + tc + j];
            *(float4*)&orow[j] = make_float4(acc[i][j] + bb.x, acc[i][j+1] + bb.y,
                                             acc[i][j+2] + bb.z, acc[i][j+3] + bb.w);
        }
    }
}

// ---------------------------------------------------------------------------
extern "C" void kernel_launch(void* const* d_in, const int* in_sizes, int n_in,
                              void* d_out, int out_size) {
    const float* x       = (const float*)d_in[0];
    const float* w_qkv   = (const float*)d_in[1];
    const float* pos_emb = (const float*)d_in[2];
    const float* w_out   = (const float*)d_in[3];
    const float* b_out   = (const float*)d_in[4];
    float* out = (float*)d_out;

    dim3 g1(1152 / BN, TOKENS / BM);          // 9 x 392
    qkv_gemm<<<g1, NTHR>>>(x, w_qkv);

    attn_kernel<<<B_ * NWIN * HEADS, 256>>>(pos_emb);

    dim3 g3(EMB / BN, TOKENS / BM);           // 3 x 392
    proj_gemm<<<g3, NTHR>>>(w_out, b_out, out);
}

// round 10
// speedup vs baseline: 1.3737x; 1.3130x over previous
#include <cuda_runtime.h>
#include <cuda_bf16.h>

// ---------------------------------------------------------------------------
// Swin shifted-window attention. R9: R8 GEMMs (guard-proven, passing) +
// attention rewritten to eliminate 32-way LDS bank conflicts in the QK stage
// (K stored transposed in smem with odd stride 57).
// ---------------------------------------------------------------------------

#define B_     16
#define HW     56
#define EMB    384
#define HEADS  12
#define HD     32
#define WS     7
#define NTOK   49          // tokens per window
#define NWIN   64          // windows per image (8x8)
#define TOKENS (B_*HW*HW)  // 50176

#define BM 128
#define BN 128
#define BK 16
#define TM 8               // rows per thread
#define TN 16              // cols per thread
#define NTHR 128           // (BM/TM)*(BN/TN) = 16*8

#define KTS 57             // kT smem row stride (odd -> conflict-free transpose)

// Scratch (device globals; guard-sanctioned)
__device__ float g_q[B_*NWIN*HEADS*NTOK*HD];
__device__ float g_k[B_*NWIN*HEADS*NTOK*HD];
__device__ float g_v[B_*NWIN*HEADS*NTOK*HD];
__device__ float g_ao[TOKENS*EMB];

// ---------------------------------------------------------------------------
// Stage 1: QKV GEMM. A = rolled x (50176 x 384), B = w_qkv (1152 x 384),
// C[i][j] = sum_k A[i][k]*B[j][k]. Scatter into windowed q/k/v layout.
// (identical to R8 passing version)
// ---------------------------------------------------------------------------
__global__ __launch_bounds__(NTHR) void qkv_gemm(const float* __restrict__ x,
                                                 const float* __restrict__ wqkv) {
    __shared__ float As[BK][BM];
    __shared__ float Bs[BK][BN];
    const int tid  = threadIdx.x;
    const int row0 = blockIdx.y * BM;
    const int col0 = blockIdx.x * BN;
    const int tr   = (tid & 15) * TM;     // 16 M-groups
    const int tc   = (tid >> 4) * TN;     // 8 N-groups

    float acc[TM][TN];
#pragma unroll
    for (int i = 0; i < TM; i++)
#pragma unroll
        for (int j = 0; j < TN; j++) acc[i][j] = 0.f;

    const int lr0 = tid >> 2;       // 0..31
    const int c4  = tid & 3;        // which float4 of the 16-col slab
    const float* arow[4];
    const float* brow[4];
#pragma unroll
    for (int l = 0; l < 4; l++) {
        int r = lr0 + l * 32;
        int m = row0 + r;
        int b = m / 3136, rem = m % 3136, h = rem / HW, w = rem % HW;
        int hs = (h + 3) % HW, ws = (w + 3) % HW;   // roll(-3,-3)
        arow[l] = x + ((b * HW + hs) * HW + ws) * EMB;
        brow[l] = wqkv + (col0 + r) * EMB;
    }

    for (int k0 = 0; k0 < EMB; k0 += BK) {
        __syncthreads();
#pragma unroll
        for (int l = 0; l < 4; l++) {
            int r = lr0 + l * 32;
            float4 a = *(const float4*)(arow[l] + k0 + c4 * 4);
            As[c4*4+0][r] = a.x; As[c4*4+1][r] = a.y;
            As[c4*4+2][r] = a.z; As[c4*4+3][r] = a.w;
            float4 bv = *(const float4*)(brow[l] + k0 + c4 * 4);
            Bs[c4*4+0][r] = bv.x; Bs[c4*4+1][r] = bv.y;
            Bs[c4*4+2][r] = bv.z; Bs[c4*4+3][r] = bv.w;
        }
        __syncthreads();
#pragma unroll
        for (int kk = 0; kk < BK; kk++) {
            float af[TM], bf[TN];
            *(float4*)&af[0]  = *(float4*)&As[kk][tr];
            *(float4*)&af[4]  = *(float4*)&As[kk][tr + 4];
            *(float4*)&bf[0]  = *(float4*)&Bs[kk][tc];
            *(float4*)&bf[4]  = *(float4*)&Bs[kk][tc + 4];
            *(float4*)&bf[8]  = *(float4*)&Bs[kk][tc + 8];
            *(float4*)&bf[12] = *(float4*)&Bs[kk][tc + 12];
#pragma unroll
            for (int i = 0; i < TM; i++)
#pragma unroll
                for (int j = 0; j < TN; j++) acc[i][j] = fmaf(af[i], bf[j], acc[i][j]);
        }
    }

    const int sel = col0 / EMB;                   // 0:q 1:k 2:v
    float* dst = (sel == 0) ? g_q : (sel == 1) ? g_k : g_v;
    const int local = col0 + tc - sel * EMB;
    const int head  = local >> 5;
    const int d0    = local & 31;                 // 0 or 16
#pragma unroll
    for (int i = 0; i < TM; i++) {
        int m = row0 + tr + i;
        int b = m / 3136, rem = m % 3136, h = rem / HW, w = rem % HW;
        int win = (h / WS) * 8 + (w / WS);
        int n   = (h % WS) * WS + (w % WS);
        float* drow = dst + (b * NWIN + win) * (HEADS * NTOK * HD)
                          + head * (NTOK * HD) + n * HD + d0;
#pragma unroll
        for (int j = 0; j < TN; j += 4) {
            *(float4*)&drow[j] = make_float4(acc[i][j], acc[i][j+1], acc[i][j+2], acc[i][j+3]);
        }
    }
}

// ---------------------------------------------------------------------------
// Stage 2: attention. One block per (b, win, head). 256 threads.
// K held TRANSPOSED in smem (kT[d][j], stride 57) -> QK stage conflict-free.
// ---------------------------------------------------------------------------
__global__ __launch_bounds__(256) void attn_kernel(const float* __restrict__ pe_g) {
    __shared__ float q[NTOK * HD];
    __shared__ float kT[HD * KTS];
    __shared__ float v[NTOK * HD];
    __shared__ float sc[NTOK][NTOK + 1];
    __shared__ float pe[169];

    const int blk = blockIdx.x;      // (b*64+win)*12 + head
    const int tid = threadIdx.x;
    const float* qp = g_q + blk * (NTOK * HD);
    const float* kp = g_k + blk * (NTOK * HD);
    const float* vp = g_v + blk * (NTOK * HD);

    // q, v: vectorized row-major copies
    for (int i4 = tid; i4 < NTOK * HD / 4; i4 += 256) {
        ((float4*)q)[i4] = ((const float4*)qp)[i4];
        ((float4*)v)[i4] = ((const float4*)vp)[i4];
    }
    // k: coalesced gmem read, transposed smem write (stride 57: conflict-free)
    for (int idx = tid; idx < NTOK * HD; idx += 256) {
        kT[(idx & 31) * KTS + (idx >> 5)] = kp[idx];
    }
    if (tid < 169) pe[tid] = pe_g[tid];
    __syncthreads();

    const int head = blk % HEADS;  (void)head;
    const int bwin = blk / HEADS;
    const int win  = bwin & 63;
    const int b    = bwin >> 6;
    const bool mUL = (win >= 56);          // last window row
    const bool mLR = ((win & 7) == 7);     // last window col
    const float scale = 0.17677669529663687f;  // 1/sqrt(32)

    // scores: lane j consecutive -> kT reads hit consecutive banks
    for (int idx = tid; idx < NTOK * NTOK; idx += 256) {
        int i = idx / NTOK, j = idx - i * NTOK;
        const float* qi = q + i * HD;
        float s = 0.f;
#pragma unroll
        for (int d = 0; d < HD; d++) s = fmaf(qi[d], kT[d * KTS + j], s);
        int xi = i / WS, yi = i - xi * WS;
        int xj = j / WS, yj = j - xj * WS;
        s = s * scale + pe[(xj - xi + 6) * 13 + (yj - yi + 6)];
        bool dead = (mUL && ((i >= 28) != (j >= 28))) ||
                    (mLR && ((yi >= 4) != (yj >= 4)));
        sc[i][j] = dead ? -1e30f : s;
    }
    __syncthreads();

    const int warp = tid >> 5, lane = tid & 31;
    for (int i = warp; i < NTOK; i += 8) {
        float mx = -1e30f;
        for (int j = lane; j < NTOK; j += 32) mx = fmaxf(mx, sc[i][j]);
#pragma unroll
        for (int o = 16; o; o >>= 1) mx = fmaxf(mx, __shfl_xor_sync(0xffffffffu, mx, o));
        float sum = 0.f;
        for (int j = lane; j < NTOK; j += 32) {
            float e = __expf(sc[i][j] - mx);
            sc[i][j] = e;
            sum += e;
        }
#pragma unroll
        for (int o = 16; o; o >>= 1) sum += __shfl_xor_sync(0xffffffffu, sum, o);
        float inv = 1.0f / sum;
        for (int j = lane; j < NTOK; j += 32) sc[i][j] *= inv;
    }
    __syncthreads();

    // out = attn @ V: lanes walk d -> v reads conflict-free; sc broadcast
    const int h0 = (win >> 3) * WS, w0 = (win & 7) * WS;
    for (int idx = tid; idx < NTOK * HD; idx += 256) {
        int i = idx >> 5, d = idx & 31;
        float o = 0.f;
#pragma unroll
        for (int j = 0; j < NTOK; j++) o = fmaf(sc[i][j], v[j * HD + d], o);
        int h = h0 + i / WS, w = w0 + i % WS;
        g_ao[((b * HW + h) * HW + w) * EMB + (blk % HEADS) * HD + d] = o;
    }
}

// ---------------------------------------------------------------------------
// Stage 3: projection GEMM (identical to R8 passing version).
// ---------------------------------------------------------------------------
__global__ __launch_bounds__(NTHR) void proj_gemm(const float* __restrict__ wout,
                                                  const float* __restrict__ bout,
                                                  float* __restrict__ out) {
    __shared__ float As[BK][BM];
    __shared__ float Bs[BK][BN];
    const int tid  = threadIdx.x;
    const int row0 = blockIdx.y * BM;
    const int col0 = blockIdx.x * BN;
    const int tr   = (tid & 15) * TM;
    const int tc   = (tid >> 4) * TN;

    float acc[TM][TN];
#pragma unroll
    for (int i = 0; i < TM; i++)
#pragma unroll
        for (int j = 0; j < TN; j++) acc[i][j] = 0.f;

    const int lr0 = tid >> 2;
    const int c4  = tid & 3;
    const float* arow[4];
    const float* brow[4];
#pragma unroll
    for (int l = 0; l < 4; l++) {
        int r = lr0 + l * 32;
        arow[l] = g_ao + (row0 + r) * EMB;
        brow[l] = wout + (col0 + r) * EMB;
    }

    for (int k0 = 0; k0 < EMB; k0 += BK) {
        __syncthreads();
#pragma unroll
        for (int l = 0; l < 4; l++) {
            int r = lr0 + l * 32;
            float4 a = *(const float4*)(arow[l] + k0 + c4 * 4);
            As[c4*4+0][r] = a.x; As[c4*4+1][r] = a.y;
            As[c4*4+2][r] = a.z; As[c4*4+3][r] = a.w;
            float4 bv = *(const float4*)(brow[l] + k0 + c4 * 4);
            Bs[c4*4+0][r] = bv.x; Bs[c4*4+1][r] = bv.y;
            Bs[c4*4+2][r] = bv.z; Bs[c4*4+3][r] = bv.w;
        }
        __syncthreads();
#pragma unroll
        for (int kk = 0; kk < BK; kk++) {
            float af[TM], bf[TN];
            *(float4*)&af[0]  = *(float4*)&As[kk][tr];
            *(float4*)&af[4]  = *(float4*)&As[kk][tr + 4];
            *(float4*)&bf[0]  = *(float4*)&Bs[kk][tc];
            *(float4*)&bf[4]  = *(float4*)&Bs[kk][tc + 4];
            *(float4*)&bf[8]  = *(float4*)&Bs[kk][tc + 8];
            *(float4*)&bf[12] = *(float4*)&Bs[kk][tc + 12];
#pragma unroll
            for (int i = 0; i < TM; i++)
#pragma unroll
                for (int j = 0; j < TN; j++) acc[i][j] = fmaf(af[i], bf[j], acc[i][j]);
        }
    }

#pragma unroll
    for (int i = 0; i < TM; i++) {
        int m = row0 + tr + i;
        int b = m / 3136, rem = m % 3136, h = rem / HW, w = rem % HW;
        int ho = (h + 3) % HW, wo = (w + 3) % HW;   // roll(+3,+3)
        float* orow = out + ((b * HW + ho) * HW + wo) * EMB + col0 + tc;
#pragma unroll
        for (int j = 0; j < TN; j += 4) {
            float4 bb = *(const float4*)&bout[col0 + tc + j];
            *(float4*)&orow[j] = make_float4(acc[i][j] + bb.x, acc[i][j+1] + bb.y,
                                             acc[i][j+2] + bb.z, acc[i][j+3] + bb.w);
        }
    }
}

// ---------------------------------------------------------------------------
extern "C" void kernel_launch(void* const* d_in, const int* in_sizes, int n_in,
                              void* d_out, int out_size) {
    const float* x       = (const float*)d_in[0];
    const float* w_qkv   = (const float*)d_in[1];
    const float* pos_emb = (const float*)d_in[2];
    const float* w_out   = (const float*)d_in[3];
    const float* b_out   = (const float*)d_in[4];
    float* out = (float*)d_out;

    dim3 g1(1152 / BN, TOKENS / BM);          // 9 x 392
    qkv_gemm<<<g1, NTHR>>>(x, w_qkv);

    attn_kernel<<<B_ * NWIN * HEADS, 256>>>(pos_emb);

    dim3 g3(EMB / BN, TOKENS / BM);           // 3 x 392
    proj_gemm<<<g3, NTHR>>>(w_out, b_out, out);
}

// round 11
// speedup vs baseline: 1.4439x; 1.0511x over previous
#include <cuda_runtime.h>
#include <cuda_bf16.h>
#include <cstdint>

// ---------------------------------------------------------------------------
// Swin shifted-window attention. R10: GEMM inner loops use Blackwell packed
// fma.rn.f32x2 (2 fp32 FMAs / issue slot, full fp32 precision). Attention
// unchanged from R9 (bank-conflict-free). First asm-without-mma experiment.
// ---------------------------------------------------------------------------

#define B_     16
#define HW     56
#define EMB    384
#define HEADS  12
#define HD     32
#define WS     7
#define NTOK   49
#define NWIN   64
#define TOKENS (B_*HW*HW)  // 50176

#define BM 128
#define BN 128
#define BK 16
#define TM 8               // rows per thread
#define TN 16              // cols per thread (8 packed pairs)
#define NTHR 128

#define KTS 57             // attn kT stride

__device__ float g_q[B_*NWIN*HEADS*NTOK*HD];
__device__ float g_k[B_*NWIN*HEADS*NTOK*HD];
__device__ float g_v[B_*NWIN*HEADS*NTOK*HD];
__device__ float g_ao[TOKENS*EMB];

// packed f32x2 helpers (named scalars / constant-indexed operands only)
#define FMA2(C, A, Bv)                                                     \
    asm("fma.rn.f32x2 %0, %1, %2, %0;" : "+l"(C) : "l"(A), "l"(Bv))
#define PACK2(O, LO, HI)                                                   \
    asm("mov.b64 %0, {%1, %2};" : "=l"(O) : "r"(LO), "r"(HI))
#define UNPACK2(LO, HI, I)                                                 \
    asm("mov.b64 {%0, %1}, %2;" : "=r"(LO), "=r"(HI) : "l"(I))

// ---------------------------------------------------------------------------
// Stage 1: QKV GEMM. C[i][j] = sum_k A_rolled[i][k]*Wqkv[j][k], scatter to
// windowed q/k/v. f32x2 inner loop.
// ---------------------------------------------------------------------------
__global__ __launch_bounds__(NTHR) void qkv_gemm(const float* __restrict__ x,
                                                 const float* __restrict__ wqkv) {
    __shared__ float As[BK][BM];
    __shared__ float Bs[BK][BN];
    const int tid  = threadIdx.x;
    const int row0 = blockIdx.y * BM;
    const int col0 = blockIdx.x * BN;
    const int tr   = (tid & 15) * TM;
    const int tc   = (tid >> 4) * TN;

    unsigned long long acc2[TM][TN/2];
#pragma unroll
    for (int i = 0; i < TM; i++)
#pragma unroll
        for (int j = 0; j < TN/2; j++) acc2[i][j] = 0ull;   // {0.f,0.f}

    const int lr0 = tid >> 2;
    const int c4  = tid & 3;
    const float* arow[4];
    const float* brow[4];
#pragma unroll
    for (int l = 0; l < 4; l++) {
        int r = lr0 + l * 32;
        int m = row0 + r;
        int b = m / 3136, rem = m % 3136, h = rem / HW, w = rem % HW;
        int hs = (h + 3) % HW, ws = (w + 3) % HW;   // roll(-3,-3)
        arow[l] = x + ((b * HW + hs) * HW + ws) * EMB;
        brow[l] = wqkv + (col0 + r) * EMB;
    }

    for (int k0 = 0; k0 < EMB; k0 += BK) {
        __syncthreads();
#pragma unroll
        for (int l = 0; l < 4; l++) {
            int r = lr0 + l * 32;
            float4 a = *(const float4*)(arow[l] + k0 + c4 * 4);
            As[c4*4+0][r] = a.x; As[c4*4+1][r] = a.y;
            As[c4*4+2][r] = a.z; As[c4*4+3][r] = a.w;
            float4 bv = *(const float4*)(brow[l] + k0 + c4 * 4);
            Bs[c4*4+0][r] = bv.x; Bs[c4*4+1][r] = bv.y;
            Bs[c4*4+2][r] = bv.z; Bs[c4*4+3][r] = bv.w;
        }
        __syncthreads();
#pragma unroll
        for (int kk = 0; kk < BK; kk++) {
            float af[TM];
            *(float4*)&af[0] = *(float4*)&As[kk][tr];
            *(float4*)&af[4] = *(float4*)&As[kk][tr + 4];
            unsigned long long b2[TN/2];
#pragma unroll
            for (int j = 0; j < TN/2; j++)
                b2[j] = *(const unsigned long long*)&Bs[kk][tc + 2*j];
#pragma unroll
            for (int i = 0; i < TM; i++) {
                unsigned long long a2;
                PACK2(a2, __float_as_uint(af[i]), __float_as_uint(af[i]));
#pragma unroll
                for (int j = 0; j < TN/2; j++) FMA2(acc2[i][j], a2, b2[j]);
            }
        }
    }

    const int sel = col0 / EMB;                   // 0:q 1:k 2:v
    float* dst = (sel == 0) ? g_q : (sel == 1) ? g_k : g_v;
    const int local = col0 + tc - sel * EMB;
    const int head  = local >> 5;
    const int d0    = local & 31;
#pragma unroll
    for (int i = 0; i < TM; i++) {
        int m = row0 + tr + i;
        int b = m / 3136, rem = m % 3136, h = rem / HW, w = rem % HW;
        int win = (h / WS) * 8 + (w / WS);
        int n   = (h % WS) * WS + (w % WS);
        float* drow = dst + (b * NWIN + win) * (HEADS * NTOK * HD)
                          + head * (NTOK * HD) + n * HD + d0;
#pragma unroll
        for (int j = 0; j < TN/2; j += 2) {
            uint32_t l0, h0_, l1, h1_;
            UNPACK2(l0, h0_, acc2[i][j]);
            UNPACK2(l1, h1_, acc2[i][j+1]);
            *(float4*)&drow[2*j] = make_float4(__uint_as_float(l0), __uint_as_float(h0_),
                                               __uint_as_float(l1), __uint_as_float(h1_));
        }
    }
}

// ---------------------------------------------------------------------------
// Stage 2: attention (identical to R9 passing version).
// ---------------------------------------------------------------------------
__global__ __launch_bounds__(256) void attn_kernel(const float* __restrict__ pe_g) {
    __shared__ float q[NTOK * HD];
    __shared__ float kT[HD * KTS];
    __shared__ float v[NTOK * HD];
    __shared__ float sc[NTOK][NTOK + 1];
    __shared__ float pe[169];

    const int blk = blockIdx.x;
    const int tid = threadIdx.x;
    const float* qp = g_q + blk * (NTOK * HD);
    const float* kp = g_k + blk * (NTOK * HD);
    const float* vp = g_v + blk * (NTOK * HD);

    for (int i4 = tid; i4 < NTOK * HD / 4; i4 += 256) {
        ((float4*)q)[i4] = ((const float4*)qp)[i4];
        ((float4*)v)[i4] = ((const float4*)vp)[i4];
    }
    for (int idx = tid; idx < NTOK * HD; idx += 256) {
        kT[(idx & 31) * KTS + (idx >> 5)] = kp[idx];
    }
    if (tid < 169) pe[tid] = pe_g[tid];
    __syncthreads();

    const int bwin = blk / HEADS;
    const int win  = bwin & 63;
    const int b    = bwin >> 6;
    const bool mUL = (win >= 56);
    const bool mLR = ((win & 7) == 7);
    const float scale = 0.17677669529663687f;

    for (int idx = tid; idx < NTOK * NTOK; idx += 256) {
        int i = idx / NTOK, j = idx - i * NTOK;
        const float* qi = q + i * HD;
        float s = 0.f;
#pragma unroll
        for (int d = 0; d < HD; d++) s = fmaf(qi[d], kT[d * KTS + j], s);
        int xi = i / WS, yi = i - xi * WS;
        int xj = j / WS, yj = j - xj * WS;
        s = s * scale + pe[(xj - xi + 6) * 13 + (yj - yi + 6)];
        bool dead = (mUL && ((i >= 28) != (j >= 28))) ||
                    (mLR && ((yi >= 4) != (yj >= 4)));
        sc[i][j] = dead ? -1e30f : s;
    }
    __syncthreads();

    const int warp = tid >> 5, lane = tid & 31;
    for (int i = warp; i < NTOK; i += 8) {
        float mx = -1e30f;
        for (int j = lane; j < NTOK; j += 32) mx = fmaxf(mx, sc[i][j]);
#pragma unroll
        for (int o = 16; o; o >>= 1) mx = fmaxf(mx, __shfl_xor_sync(0xffffffffu, mx, o));
        float sum = 0.f;
        for (int j = lane; j < NTOK; j += 32) {
            float e = __expf(sc[i][j] - mx);
            sc[i][j] = e;
            sum += e;
        }
#pragma unroll
        for (int o = 16; o; o >>= 1) sum += __shfl_xor_sync(0xffffffffu, sum, o);
        float inv = 1.0f / sum;
        for (int j = lane; j < NTOK; j += 32) sc[i][j] *= inv;
    }
    __syncthreads();

    const int h0 = (win >> 3) * WS, w0 = (win & 7) * WS;
    for (int idx = tid; idx < NTOK * HD; idx += 256) {
        int i = idx >> 5, d = idx & 31;
        float o = 0.f;
#pragma unroll
        for (int j = 0; j < NTOK; j++) o = fmaf(sc[i][j], v[j * HD + d], o);
        int h = h0 + i / WS, w = w0 + i % WS;
        g_ao[((b * HW + h) * HW + w) * EMB + (blk % HEADS) * HD + d] = o;
    }
}

// ---------------------------------------------------------------------------
// Stage 3: projection GEMM, f32x2 inner loop. roll(+3,+3) + bias on store.
// ---------------------------------------------------------------------------
__global__ __launch_bounds__(NTHR) void proj_gemm(const float* __restrict__ wout,
                                                  const float* __restrict__ bout,
                                                  float* __restrict__ out) {
    __shared__ float As[BK][BM];
    __shared__ float Bs[BK][BN];
    const int tid  = threadIdx.x;
    const int row0 = blockIdx.y * BM;
    const int col0 = blockIdx.x * BN;
    const int tr   = (tid & 15) * TM;
    const int tc   = (tid >> 4) * TN;

    unsigned long long acc2[TM][TN/2];
#pragma unroll
    for (int i = 0; i < TM; i++)
#pragma unroll
        for (int j = 0; j < TN/2; j++) acc2[i][j] = 0ull;

    const int lr0 = tid >> 2;
    const int c4  = tid & 3;
    const float* arow[4];
    const float* brow[4];
#pragma unroll
    for (int l = 0; l < 4; l++) {
        int r = lr0 + l * 32;
        arow[l] = g_ao + (row0 + r) * EMB;
        brow[l] = wout + (col0 + r) * EMB;
    }

    for (int k0 = 0; k0 < EMB; k0 += BK) {
        __syncthreads();
#pragma unroll
        for (int l = 0; l < 4; l++) {
            int r = lr0 + l * 32;
            float4 a = *(const float4*)(arow[l] + k0 + c4 * 4);
            As[c4*4+0][r] = a.x; As[c4*4+1][r] = a.y;
            As[c4*4+2][r] = a.z; As[c4*4+3][r] = a.w;
            float4 bv = *(const float4*)(brow[l] + k0 + c4 * 4);
            Bs[c4*4+0][r] = bv.x; Bs[c4*4+1][r] = bv.y;
            Bs[c4*4+2][r] = bv.z; Bs[c4*4+3][r] = bv.w;
        }
        __syncthreads();
#pragma unroll
        for (int kk = 0; kk < BK; kk++) {
            float af[TM];
            *(float4*)&af[0] = *(float4*)&As[kk][tr];
            *(float4*)&af[4] = *(float4*)&As[kk][tr + 4];
            unsigned long long b2[TN/2];
#pragma unroll
            for (int j = 0; j < TN/2; j++)
                b2[j] = *(const unsigned long long*)&Bs[kk][tc + 2*j];
#pragma unroll
            for (int i = 0; i < TM; i++) {
                unsigned long long a2;
                PACK2(a2, __float_as_uint(af[i]), __float_as_uint(af[i]));
#pragma unroll
                for (int j = 0; j < TN/2; j++) FMA2(acc2[i][j], a2, b2[j]);
            }
        }
    }

#pragma unroll
    for (int i = 0; i < TM; i++) {
        int m = row0 + tr + i;
        int b = m / 3136, rem = m % 3136, h = rem / HW, w = rem % HW;
        int ho = (h + 3) % HW, wo = (w + 3) % HW;   // roll(+3,+3)
        float* orow = out + ((b * HW + ho) * HW + wo) * EMB + col0 + tc;
#pragma unroll
        for (int j = 0; j < TN/2; j += 2) {
            uint32_t l0, h0_, l1, h1_;
            UNPACK2(l0, h0_, acc2[i][j]);
            UNPACK2(l1, h1_, acc2[i][j+1]);
            float4 bb = *(const float4*)&bout[col0 + tc + 2*j];
            *(float4*)&orow[2*j] = make_float4(__uint_as_float(l0) + bb.x,
                                               __uint_as_float(h0_) + bb.y,
                                               __uint_as_float(l1) + bb.z,
                                               __uint_as_float(h1_) + bb.w);
        }
    }
}

// ---------------------------------------------------------------------------
extern "C" void kernel_launch(void* const* d_in, const int* in_sizes, int n_in,
                              void* d_out, int out_size) {
    const float* x       = (const float*)d_in[0];
    const float* w_qkv   = (const float*)d_in[1];
    const float* pos_emb = (const float*)d_in[2];
    const float* w_out   = (const float*)d_in[3];
    const float* b_out   = (const float*)d_in[4];
    float* out = (float*)d_out;

    dim3 g1(1152 / BN, TOKENS / BM);          // 9 x 392
    qkv_gemm<<<g1, NTHR>>>(x, w_qkv);

    attn_kernel<<<B_ * NWIN * HEADS, 256>>>(pos_emb);

    dim3 g3(EMB / BN, TOKENS / BM);           // 3 x 392
    proj_gemm<<<g3, NTHR>>>(w_out, b_out, out);
}